// round 6
// baseline (speedup 1.0000x reference)
#include <cuda_runtime.h>
#include <cuda_bf16.h>
#include <cstdint>

#define NNODES 200000
#define CCH    256
#define VCD    48      // 16 * 3
#define MSEG   50000

typedef unsigned long long u64;

// Scratch (allocation-free rule: __device__ globals)
__device__ float g_s_sum[MSEG * CCH];   // 51.2 MB
__device__ float g_v_sum[MSEG * VCD];   // 9.6 MB
__device__ float g_cnt[MSEG];

// ---- packed f32x2 helpers (Blackwell FFMA2 path; ptxas never auto-fuses) ----
__device__ __forceinline__ u64 pack2_dup(float a) {
    u64 r; asm("mov.b64 %0, {%1, %1};" : "=l"(r) : "f"(a)); return r;
}
__device__ __forceinline__ void ffma2(u64& d, u64 a, u64 b) {
    asm("fma.rn.f32x2 %0, %1, %2, %0;" : "+l"(d) : "l"(a), "l"(b));
}
__device__ __forceinline__ void unpack2(u64 v, float& lo, float& hi) {
    asm("mov.b64 {%0, %1}, %2;" : "=f"(lo), "=f"(hi) : "l"(v));
}

// ---------------------------------------------------------------------------
// Kernel 1: zero the scratch accumulators
// ---------------------------------------------------------------------------
__global__ void mp_zero_kernel() {
    int idx    = blockIdx.x * blockDim.x + threadIdx.x;
    int stride = gridDim.x * blockDim.x;
    const float4 z = make_float4(0.f, 0.f, 0.f, 0.f);
    const int nA = MSEG * CCH / 4;
    for (int i = idx; i < nA; i += stride) reinterpret_cast<float4*>(g_s_sum)[i] = z;
    const int nB = MSEG * VCD / 4;
    for (int i = idx; i < nB; i += stride) reinterpret_cast<float4*>(g_v_sum)[i] = z;
    const int nC = MSEG / 4;
    for (int i = idx; i < nC; i += stride) reinterpret_cast<float4*>(g_cnt)[i] = z;
}

// ---------------------------------------------------------------------------
// Kernel 2: scatter-sum s and v rows into per-motif accumulators.
// One warp per node row (grid-stride). float4 global loads, scalar REDs.
// motif_batch arrives as int32 (JAX x64-off downgrades int64).
// ---------------------------------------------------------------------------
__global__ void mp_scatter_kernel(const float* __restrict__ s,
                                  const float* __restrict__ v,
                                  const int* __restrict__ seg) {
    int gwarp  = (blockIdx.x * blockDim.x + threadIdx.x) >> 5;
    int lane   = threadIdx.x & 31;
    int nwarps = (gridDim.x * blockDim.x) >> 5;

    for (int row = gwarp; row < NNODES; row += nwarps) {
        int m = seg[row];

        const float4* srow = reinterpret_cast<const float4*>(s + (size_t)row * CCH);
        float* dsts = g_s_sum + (size_t)m * CCH;
#pragma unroll
        for (int i = 0; i < 2; i++) {
            int f4i = lane + 32 * i;
            float4 val = srow[f4i];
            int base = f4i * 4;
            atomicAdd(dsts + base + 0, val.x);
            atomicAdd(dsts + base + 1, val.y);
            atomicAdd(dsts + base + 2, val.z);
            atomicAdd(dsts + base + 3, val.w);
        }

        if (lane < 12) {
            float4 val = reinterpret_cast<const float4*>(v + (size_t)row * VCD)[lane];
            float* dstv = g_v_sum + (size_t)m * VCD + lane * 4;
            atomicAdd(dstv + 0, val.x);
            atomicAdd(dstv + 1, val.y);
            atomicAdd(dstv + 2, val.z);
            atomicAdd(dstv + 3, val.w);
        }

        if (lane == 0) atomicAdd(&g_cnt[m], 1.0f);
    }
}

// ---------------------------------------------------------------------------
// Kernel 3: s_out[m, j] = (sum_k g_s_sum[m,k] * Ws[j,k]) / cnt[m] + bs[j]
// Tiled SGEMM, FFMA2 (fma.rn.f32x2) inner loop: 2 fp32 FMAs per issue.
// BM=128, BN=128, BK=16, 256 threads, 8x8 per thread (stored as 8x4 f32x2).
// ---------------------------------------------------------------------------
#define BM 128
#define BN 128
#define BK 16
#define TM 8
#define TN 8

__global__ __launch_bounds__(256, 2)
void mp_gemm_kernel(const float* __restrict__ Ws,
                    const float* __restrict__ bs,
                    float* __restrict__ out_s) {
    __shared__ __align__(16) float sA[BK][BM + 4];
    __shared__ __align__(16) float sB[BK][BN + 4];

    const int tid = threadIdx.x;           // 0..255
    const int bm  = blockIdx.x * BM;
    const int bn  = blockIdx.y * BN;
    const int tx  = tid & 15;              // N groups of 8
    const int ty  = tid >> 4;              // M groups of 8

    u64 acc2[TM][TN / 2];
#pragma unroll
    for (int i = 0; i < TM; i++)
#pragma unroll
        for (int j = 0; j < TN / 2; j++) acc2[i][j] = 0ull;

    for (int k0 = 0; k0 < CCH; k0 += BK) {
        // Load A tile (g_s_sum[bm.., k0..]) transposed into sA[k][m]
#pragma unroll
        for (int it = 0; it < 2; it++) {
            int t  = tid + it * 256;       // 0..511
            int r  = t >> 2;               // 0..127
            int kc = (t & 3) * 4;          // 0,4,8,12
            int grow = bm + r;
            float4 val = make_float4(0.f, 0.f, 0.f, 0.f);
            if (grow < MSEG)
                val = *reinterpret_cast<const float4*>(g_s_sum + (size_t)grow * CCH + k0 + kc);
            sA[kc + 0][r] = val.x;
            sA[kc + 1][r] = val.y;
            sA[kc + 2][r] = val.z;
            sA[kc + 3][r] = val.w;
        }
        // Load B tile (Ws[bn.., k0..]) transposed into sB[k][j]
#pragma unroll
        for (int it = 0; it < 2; it++) {
            int t  = tid + it * 256;
            int j  = t >> 2;
            int kc = (t & 3) * 4;
            float4 val = *reinterpret_cast<const float4*>(Ws + (size_t)(bn + j) * CCH + k0 + kc);
            sB[kc + 0][j] = val.x;
            sB[kc + 1][j] = val.y;
            sB[kc + 2][j] = val.z;
            sB[kc + 3][j] = val.w;
        }
        __syncthreads();

#pragma unroll
        for (int kk = 0; kk < BK; kk++) {
            // b pairs: 4 x LDS.64 of adjacent floats
            u64 b2[TN / 2];
#pragma unroll
            for (int t = 0; t < TN / 2; t++)
                b2[t] = *reinterpret_cast<const u64*>(&sB[kk][tx * TN + 2 * t]);
            // a scalars -> duplicated pairs
            u64 a2[TM];
#pragma unroll
            for (int i = 0; i < TM; i++)
                a2[i] = pack2_dup(sA[kk][ty * TM + i]);
#pragma unroll
            for (int i = 0; i < TM; i++)
#pragma unroll
                for (int t = 0; t < TN / 2; t++)
                    ffma2(acc2[i][t], a2[i], b2[t]);
        }
        __syncthreads();
    }

    // Epilogue: /count, +bias
    float bvals[TN];
#pragma unroll
    for (int j = 0; j < TN; j++) bvals[j] = bs[bn + tx * TN + j];

#pragma unroll
    for (int i = 0; i < TM; i++) {
        int m = bm + ty * TM + i;
        if (m >= MSEG) continue;
        float inv = 1.0f / fmaxf(g_cnt[m], 1.0f);
        float* orow = out_s + (size_t)m * CCH + bn + tx * TN;
#pragma unroll
        for (int t = 0; t < TN / 2; t++) {
            float lo, hi;
            unpack2(acc2[i][t], lo, hi);
            orow[2 * t + 0] = lo * inv + bvals[2 * t + 0];
            orow[2 * t + 1] = hi * inv + bvals[2 * t + 1];
        }
    }
}

// ---------------------------------------------------------------------------
// Kernel 4: v_out[m, o, d] = (sum_c g_v_sum[m,c,d] * Wv[o,c]) / cnt[m] + bv[o]
// ---------------------------------------------------------------------------
#define MOTIFS_PB 16

__global__ void mp_vtrans_kernel(const float* __restrict__ Wv,
                                 const float* __restrict__ bv,
                                 float* __restrict__ out_v) {
    __shared__ float sW[256];
    __shared__ float sb[16];
    __shared__ float sv[MOTIFS_PB * VCD];
    __shared__ float sc[MOTIFS_PB];

    const int tid = threadIdx.x;  // 256
    sW[tid] = Wv[tid];
    if (tid < 16) sb[tid] = bv[tid];

    const int m0 = blockIdx.x * MOTIFS_PB;   // 50000 = 16 * 3125
    for (int i = tid; i < MOTIFS_PB * VCD; i += 256)
        sv[i] = g_v_sum[(size_t)m0 * VCD + i];
    if (tid < MOTIFS_PB)
        sc[tid] = 1.0f / fmaxf(g_cnt[m0 + tid], 1.0f);
    __syncthreads();

    for (int i = tid; i < MOTIFS_PB * VCD; i += 256) {
        int lm = i / VCD;
        int od = i - lm * VCD;
        int o  = od / 3;
        int d  = od - o * 3;
        float a = 0.f;
#pragma unroll
        for (int c = 0; c < 16; c++)
            a = fmaf(sW[o * 16 + c], sv[lm * VCD + c * 3 + d], a);
        out_v[(size_t)(m0 + lm) * VCD + od] = a * sc[lm] + sb[o];
    }
}

// ---------------------------------------------------------------------------
extern "C" void kernel_launch(void* const* d_in, const int* in_sizes, int n_in,
                              void* d_out, int out_size) {
    const float* s   = (const float*)d_in[0];       // [N, 256]
    const float* v   = (const float*)d_in[1];       // [N, 16, 3]
    const int*   seg = (const int*)d_in[2];         // [N] int32
    const float* Ws  = (const float*)d_in[3];       // [256, 256]
    const float* bs  = (const float*)d_in[4];       // [256]
    const float* Wv  = (const float*)d_in[5];       // [16, 16]
    const float* bv  = (const float*)d_in[6];       // [16]

    float* out_s = (float*)d_out;                        // [M, 256]
    float* out_v = (float*)d_out + (size_t)MSEG * CCH;   // [M, 16, 3]

    mp_zero_kernel<<<2048, 256>>>();
    mp_scatter_kernel<<<4096, 256>>>(s, v, seg);

    dim3 ggrid((MSEG + BM - 1) / BM, CCH / BN);          // (391, 2)
    mp_gemm_kernel<<<ggrid, 256>>>(Ws, bs, out_s);

    mp_vtrans_kernel<<<MSEG / MOTIFS_PB, 256>>>(Wv, bv, out_v);
}

// round 8
// speedup vs baseline: 1.3387x; 1.3387x over previous
#include <cuda_runtime.h>
#include <cuda_bf16.h>
#include <cstdint>

#define NNODES 200000
#define CCH    256
#define VCD    48      // 16 * 3
#define MSEG   50000

typedef unsigned long long u64;

// Scratch (allocation-free rule: __device__ globals)
__device__ float g_s_sum[MSEG * CCH];   // 51.2 MB (motif s sums)
__device__ float g_inv[MSEG];           // 1 / max(count, 1)
__device__ int   g_cnt_i[MSEG];         // histogram
__device__ int   g_off[MSEG];           // segment base offsets (arbitrary order)
__device__ int   g_pos[NNODES];         // rank of node within its motif
__device__ int   g_perm[NNODES];        // node ids grouped by motif
__device__ int   g_total;               // running offset allocator

// ---- packed f32x2 helpers ----
__device__ __forceinline__ u64 pack2_dup(float a) {
    u64 r; asm("mov.b64 %0, {%1, %1};" : "=l"(r) : "f"(a)); return r;
}
__device__ __forceinline__ void ffma2(u64& d, u64 a, u64 b) {
    asm("fma.rn.f32x2 %0, %1, %2, %0;" : "+l"(d) : "l"(a), "l"(b));
}
__device__ __forceinline__ void unpack2(u64 v, float& lo, float& hi) {
    asm("mov.b64 {%0, %1}, %2;" : "=f"(lo), "=f"(hi) : "l"(v));
}

// ---------------------------------------------------------------------------
// Kernel 1: zero histogram + allocator
// ---------------------------------------------------------------------------
__global__ void mp_zero_kernel() {
    int i = blockIdx.x * blockDim.x + threadIdx.x;
    if (i < MSEG) g_cnt_i[i] = 0;
    if (i == 0)   g_total = 0;
}

// ---------------------------------------------------------------------------
// Kernel 2: histogram + per-node rank within motif
// ---------------------------------------------------------------------------
__global__ void mp_hist_kernel(const int* __restrict__ seg) {
    int i = blockIdx.x * blockDim.x + threadIdx.x;
    if (i < NNODES) {
        int m = seg[i];
        g_pos[i] = atomicAdd(&g_cnt_i[m], 1);
    }
}

// ---------------------------------------------------------------------------
// Kernel 3: segment base offsets (warp-aggregated; segment order irrelevant)
// ---------------------------------------------------------------------------
__global__ void mp_offsets_kernel() {
    int i    = blockIdx.x * blockDim.x + threadIdx.x;
    int lane = threadIdx.x & 31;
    int c = (i < MSEG) ? g_cnt_i[i] : 0;
    // warp inclusive scan
    int incl = c;
#pragma unroll
    for (int off = 1; off < 32; off <<= 1) {
        int n = __shfl_up_sync(0xffffffffu, incl, off);
        if (lane >= off) incl += n;
    }
    int excl  = incl - c;
    int total = __shfl_sync(0xffffffffu, incl, 31);
    int base  = 0;
    if (lane == 0) base = atomicAdd(&g_total, total);
    base = __shfl_sync(0xffffffffu, base, 0);
    if (i < MSEG) {
        g_off[i] = base + excl;
        g_inv[i] = 1.0f / fmaxf((float)c, 1.0f);
    }
}

// ---------------------------------------------------------------------------
// Kernel 4: build permutation (nodes grouped by motif)
// ---------------------------------------------------------------------------
__global__ void mp_perm_kernel(const int* __restrict__ seg) {
    int i = blockIdx.x * blockDim.x + threadIdx.x;
    if (i < NNODES) {
        g_perm[g_off[seg[i]] + g_pos[i]] = i;
    }
}

// ---------------------------------------------------------------------------
// Kernel 5: segmented pooling (warp per motif) + fused v-transform.
//   g_s_sum[m, :] = sum of s rows (written directly, no atomics, no pre-zero)
//   out_v[m, o, d] = (sum_c Wv[o,c] * v_sum[c,d]) * inv + bv[o]
// ---------------------------------------------------------------------------
#define POOL_WPB 8

__global__ __launch_bounds__(256)
void mp_pool_kernel(const float* __restrict__ s,
                    const float* __restrict__ v,
                    const float* __restrict__ Wv,
                    const float* __restrict__ bv,
                    float* __restrict__ out_v) {
    __shared__ __align__(16) float sW[256];
    __shared__ float sb[16];
    __shared__ __align__(16) float sv[POOL_WPB][VCD];

    const int tid  = threadIdx.x;
    const int lane = tid & 31;
    const int w    = tid >> 5;

    sW[tid] = Wv[tid];
    if (tid < 16) sb[tid] = bv[tid];
    __syncthreads();

    const int m = blockIdx.x * POOL_WPB + w;   // 6250 * 8 = 50000 exact
    const int start = g_off[m];
    const int len   = g_cnt_i[m];

    float4 a0 = make_float4(0.f, 0.f, 0.f, 0.f);
    float4 a1 = make_float4(0.f, 0.f, 0.f, 0.f);
    float4 av = make_float4(0.f, 0.f, 0.f, 0.f);

    for (int n = 0; n < len; n++) {
        int row = g_perm[start + n];
        const float4* sr = reinterpret_cast<const float4*>(s + (size_t)row * CCH);
        float4 x0 = sr[lane];
        float4 x1 = sr[lane + 32];
        a0.x += x0.x; a0.y += x0.y; a0.z += x0.z; a0.w += x0.w;
        a1.x += x1.x; a1.y += x1.y; a1.z += x1.z; a1.w += x1.w;
        if (lane < 12) {
            float4 xv = reinterpret_cast<const float4*>(v + (size_t)row * VCD)[lane];
            av.x += xv.x; av.y += xv.y; av.z += xv.z; av.w += xv.w;
        }
    }

    // write s sums (coalesced float4)
    float4* ds = reinterpret_cast<float4*>(g_s_sum + (size_t)m * CCH);
    ds[lane]      = a0;
    ds[lane + 32] = a1;

    // stage v sums in smem for the 16x16 transform
    if (lane < 12)
        reinterpret_cast<float4*>(&sv[w][0])[lane] = av;
    __syncwarp();

    const float inv = 1.0f / fmaxf((float)len, 1.0f);
    if (lane < 16) {
        int o = lane;
        float r0 = 0.f, r1 = 0.f, r2 = 0.f;
#pragma unroll
        for (int c = 0; c < 16; c++) {
            float wv = sW[o * 16 + c];
            r0 = fmaf(wv, sv[w][c * 3 + 0], r0);
            r1 = fmaf(wv, sv[w][c * 3 + 1], r1);
            r2 = fmaf(wv, sv[w][c * 3 + 2], r2);
        }
        float bo = sb[o];
        float* ov = out_v + (size_t)m * VCD + o * 3;
        ov[0] = r0 * inv + bo;
        ov[1] = r1 * inv + bo;
        ov[2] = r2 * inv + bo;
    }
}

// ---------------------------------------------------------------------------
// Kernel 6: s_out[m, j] = (sum_k g_s_sum[m,k] * Ws[j,k]) * inv[m] + bs[j]
// Tiled SGEMM, FFMA2 inner loop. BM=BN=128, BK=16, 256 threads, 8x8/thread.
// ---------------------------------------------------------------------------
#define BM 128
#define BN 128
#define BK 16
#define TM 8
#define TN 8

__global__ __launch_bounds__(256, 2)
void mp_gemm_kernel(const float* __restrict__ Ws,
                    const float* __restrict__ bs,
                    float* __restrict__ out_s) {
    __shared__ __align__(16) float sA[BK][BM + 4];
    __shared__ __align__(16) float sB[BK][BN + 4];

    const int tid = threadIdx.x;
    const int bm  = blockIdx.x * BM;
    const int bn  = blockIdx.y * BN;
    const int tx  = tid & 15;
    const int ty  = tid >> 4;

    u64 acc2[TM][TN / 2];
#pragma unroll
    for (int i = 0; i < TM; i++)
#pragma unroll
        for (int j = 0; j < TN / 2; j++) acc2[i][j] = 0ull;

    for (int k0 = 0; k0 < CCH; k0 += BK) {
#pragma unroll
        for (int it = 0; it < 2; it++) {
            int t  = tid + it * 256;
            int r  = t >> 2;
            int kc = (t & 3) * 4;
            int grow = bm + r;
            float4 val = make_float4(0.f, 0.f, 0.f, 0.f);
            if (grow < MSEG)
                val = *reinterpret_cast<const float4*>(g_s_sum + (size_t)grow * CCH + k0 + kc);
            sA[kc + 0][r] = val.x;
            sA[kc + 1][r] = val.y;
            sA[kc + 2][r] = val.z;
            sA[kc + 3][r] = val.w;
        }
#pragma unroll
        for (int it = 0; it < 2; it++) {
            int t  = tid + it * 256;
            int j  = t >> 2;
            int kc = (t & 3) * 4;
            float4 val = *reinterpret_cast<const float4*>(Ws + (size_t)(bn + j) * CCH + k0 + kc);
            sB[kc + 0][j] = val.x;
            sB[kc + 1][j] = val.y;
            sB[kc + 2][j] = val.z;
            sB[kc + 3][j] = val.w;
        }
        __syncthreads();

#pragma unroll
        for (int kk = 0; kk < BK; kk++) {
            u64 b2[TN / 2];
#pragma unroll
            for (int t = 0; t < TN / 2; t++)
                b2[t] = *reinterpret_cast<const u64*>(&sB[kk][tx * TN + 2 * t]);
            u64 a2[TM];
#pragma unroll
            for (int i = 0; i < TM; i++)
                a2[i] = pack2_dup(sA[kk][ty * TM + i]);
#pragma unroll
            for (int i = 0; i < TM; i++)
#pragma unroll
                for (int t = 0; t < TN / 2; t++)
                    ffma2(acc2[i][t], a2[i], b2[t]);
        }
        __syncthreads();
    }

    float bvals[TN];
#pragma unroll
    for (int j = 0; j < TN; j++) bvals[j] = bs[bn + tx * TN + j];

#pragma unroll
    for (int i = 0; i < TM; i++) {
        int m = bm + ty * TM + i;
        if (m >= MSEG) continue;
        float inv = g_inv[m];
        float* orow = out_s + (size_t)m * CCH + bn + tx * TN;
#pragma unroll
        for (int t = 0; t < TN / 2; t++) {
            float lo, hi;
            unpack2(acc2[i][t], lo, hi);
            orow[2 * t + 0] = lo * inv + bvals[2 * t + 0];
            orow[2 * t + 1] = hi * inv + bvals[2 * t + 1];
        }
    }
}

// ---------------------------------------------------------------------------
extern "C" void kernel_launch(void* const* d_in, const int* in_sizes, int n_in,
                              void* d_out, int out_size) {
    const float* s   = (const float*)d_in[0];       // [N, 256]
    const float* v   = (const float*)d_in[1];       // [N, 16, 3]
    const int*   seg = (const int*)d_in[2];         // [N] int32
    const float* Ws  = (const float*)d_in[3];       // [256, 256]
    const float* bs  = (const float*)d_in[4];       // [256]
    const float* Wv  = (const float*)d_in[5];       // [16, 16]
    const float* bv  = (const float*)d_in[6];       // [16]

    float* out_s = (float*)d_out;                        // [M, 256]
    float* out_v = (float*)d_out + (size_t)MSEG * CCH;   // [M, 16, 3]

    mp_zero_kernel<<<(MSEG + 255) / 256, 256>>>();
    mp_hist_kernel<<<(NNODES + 255) / 256, 256>>>(seg);
    mp_offsets_kernel<<<(MSEG + 255) / 256, 256>>>();
    mp_perm_kernel<<<(NNODES + 255) / 256, 256>>>(seg);
    mp_pool_kernel<<<MSEG / POOL_WPB, 256>>>(s, v, Wv, bv, out_v);

    dim3 ggrid((MSEG + BM - 1) / BM, CCH / BN);          // (391, 2)
    mp_gemm_kernel<<<ggrid, 256>>>(Ws, bs, out_s);
}